// round 6
// baseline (speedup 1.0000x reference)
#include <cuda_runtime.h>
#include <cuda_bf16.h>
#include <cstdint>
#include <math.h>

// C = normalize_rows(ex) @ normalize_rows(ey)^T  [8192 x 8192]
// rowmax/colmax -> entropy terms. INT8 IMMA mma.sync GEMM (scale 127),
// s32 accumulators, integer max epilogue, final reduction fused into the
// last GEMM CTA. C never materialized.

#define NROWS 8192
#define KDIM  768
#define BM 128
#define BN 256
#define BK 128                   // 128 s8 = 128B rows
#define NK (KDIM / BK)           // 6
#define NSTAGE 4
#define A_BYTES (BM * BK)        // 16384
#define B_BYTES (BN * BK)        // 32768
#define STAGE_BYTES (A_BYTES + B_BYTES)    // 49152
#define SMEM_TOTAL (NSTAGE * STAGE_BYTES)  // 196608
#define QSCALE 127.0f
#define INV_Q2 (1.0f / (127.0f * 127.0f))
#define NCTA (NROWS / BM * NROWS / BN)     // 2048

__device__ __align__(128) signed char g_Xq[NROWS * KDIM];
__device__ __align__(128) signed char g_Yq[NROWS * KDIM];
__device__ int g_rowmax[NROWS];
__device__ int g_colmax[NROWS];
__device__ int g_done;

__device__ __forceinline__ uint32_t s2u(const void* p) {
    return (uint32_t)__cvta_generic_to_shared(p);
}

// ---------------------------------------------------------------------------
// Kernel 1: row-normalize fp32 -> s8 (x127). Warp per row, 8 rows per block.
// ---------------------------------------------------------------------------
__global__ __launch_bounds__(256) void norm_kernel(const float* __restrict__ ex,
                                                   const float* __restrict__ ey) {
    int warp = threadIdx.x >> 5, lane = threadIdx.x & 31;
    int row = blockIdx.x * 8 + warp;
    const float* src;
    signed char* dst;
    if (row < NROWS) { src = ex + (size_t)row * KDIM; dst = g_Xq + (size_t)row * KDIM; }
    else { row -= NROWS; src = ey + (size_t)row * KDIM; dst = g_Yq + (size_t)row * KDIM; }

    float4 v[6];
    float ss = 0.f;
    #pragma unroll
    for (int w = 0; w < 6; w++) {
        v[w] = ((const float4*)src)[lane + w * 32];
        ss += v[w].x * v[w].x + v[w].y * v[w].y + v[w].z * v[w].z + v[w].w * v[w].w;
    }
    #pragma unroll
    for (int o = 16; o > 0; o >>= 1) ss += __shfl_xor_sync(0xffffffffu, ss, o);
    float inv = QSCALE / fmaxf(sqrtf(ss), 1e-8f);
    #pragma unroll
    for (int w = 0; w < 6; w++) {
        int a = __float2int_rn(v[w].x * inv);
        int b = __float2int_rn(v[w].y * inv);
        int c = __float2int_rn(v[w].z * inv);
        int d = __float2int_rn(v[w].w * inv);
        uint32_t packed = (uint32_t)(a & 0xFF) | ((uint32_t)(b & 0xFF) << 8) |
                          ((uint32_t)(c & 0xFF) << 16) | ((uint32_t)(d & 0xFF) << 24);
        ((uint32_t*)dst)[lane + w * 32] = packed;
    }
}

__global__ void init_kernel() {
    int t = blockIdx.x * blockDim.x + threadIdx.x;
    if (t < NROWS) { g_rowmax[t] = -2000000000; g_colmax[t] = -2000000000; }
    if (t == 0) g_done = 0;
}

// ---------------------------------------------------------------------------
// Kernel 3: s8 IMMA GEMM, 128x256 CTA tile, 16 warps, 64x32 warp tile,
// BK=128 (128B rows), 4-stage cp.async, fused row/col max + fused finalize.
// Swizzle: sw(row, kh) = row*128 + ((kh ^ (row & 7)) << 4), kh = 16B chunk.
// ---------------------------------------------------------------------------
__global__ __launch_bounds__(512, 1) void gemm_max_kernel(float* __restrict__ out) {
    extern __shared__ __align__(1024) char smem[];
    __shared__ int srow[BM];
    __shared__ int scol[BN];
    __shared__ int is_last;

    const int tid = threadIdx.x;
    const int warp = tid >> 5, lane = tid & 31;
    const int m0 = blockIdx.y * BM;
    const int n0 = blockIdx.x * BN;
    const int wm = (warp >> 3) * 64;   // 0 or 64
    const int wn = (warp & 7) * 32;    // 0..224

    if (tid < BM) srow[tid] = -2000000000;
    if (tid < BN) scol[tid] = -2000000000;

    int acc[4][4][4];
    #pragma unroll
    for (int a = 0; a < 4; a++)
        #pragma unroll
        for (int b = 0; b < 4; b++)
            #pragma unroll
            for (int c = 0; c < 4; c++) acc[a][b][c] = 0;

    auto prefetch = [&](int stage, int k0, bool valid) {
        if (valid) {
            char* sa = smem + stage * STAGE_BYTES;
            char* sb = sa + A_BYTES;
            #pragma unroll
            for (int j = 0; j < 6; j++) {
                int i = tid + j * 512;  // 16B chunks: A 1024, B 2048
                const signed char* src;
                uint32_t dst;
                if (i < 1024) {         // A: 128 rows x 8 chunks
                    int row = i >> 3, kh = i & 7;
                    src = g_Xq + (size_t)(m0 + row) * KDIM + k0 + kh * 16;
                    dst = s2u(sa + row * 128 + ((kh ^ (row & 7)) << 4));
                } else {                // B: 256 rows x 8 chunks
                    int idx = i - 1024;
                    int row = idx >> 3, kh = idx & 7;
                    src = g_Yq + (size_t)(n0 + row) * KDIM + k0 + kh * 16;
                    dst = s2u(sb + row * 128 + ((kh ^ (row & 7)) << 4));
                }
                asm volatile("cp.async.cg.shared.global [%0], [%1], 16;"
                             :: "r"(dst), "l"(src));
            }
        }
        asm volatile("cp.async.commit_group;");
    };

    prefetch(0, 0, true);
    prefetch(1, BK, true);
    prefetch(2, 2 * BK, true);

    for (int it = 0; it < NK; it++) {
        asm volatile("cp.async.wait_group 2;");
        __syncthreads();
        prefetch((it + 3) & 3, (it + 3) * BK, it + 3 < NK);

        const uint32_t sa = s2u(smem) + (uint32_t)(it & 3) * STAGE_BYTES;
        const uint32_t sb = sa + A_BYTES;

        #pragma unroll
        for (int kk = 0; kk < 4; kk++) {   // 4 x k32 per BK=128
            uint32_t af[4][4], bf[2][4];
            #pragma unroll
            for (int mt = 0; mt < 4; mt++) {
                int row = wm + mt * 16 + (lane & 15);
                int kh = kk * 2 + (lane >> 4);
                uint32_t addr = sa + row * 128 + ((kh ^ (row & 7)) << 4);
                asm volatile(
                    "ldmatrix.sync.aligned.m8n8.x4.shared.b16 {%0,%1,%2,%3}, [%4];"
                    : "=r"(af[mt][0]), "=r"(af[mt][1]),
                      "=r"(af[mt][2]), "=r"(af[mt][3]) : "r"(addr));
            }
            #pragma unroll
            for (int p = 0; p < 2; p++) {
                int n = wn + p * 16 + ((lane >> 4) << 3) + (lane & 7);
                int kh = kk * 2 + ((lane >> 3) & 1);
                uint32_t addr = sb + n * 128 + ((kh ^ (n & 7)) << 4);
                asm volatile(
                    "ldmatrix.sync.aligned.m8n8.x4.shared.b16 {%0,%1,%2,%3}, [%4];"
                    : "=r"(bf[p][0]), "=r"(bf[p][1]),
                      "=r"(bf[p][2]), "=r"(bf[p][3]) : "r"(addr));
            }
            #pragma unroll
            for (int mt = 0; mt < 4; mt++)
                #pragma unroll
                for (int nt = 0; nt < 4; nt++) {
                    asm volatile(
                        "mma.sync.aligned.m16n8k32.row.col.s32.s8.s8.s32 "
                        "{%0,%1,%2,%3}, {%4,%5,%6,%7}, {%8,%9}, {%0,%1,%2,%3};\n"
                        : "+r"(acc[mt][nt][0]), "+r"(acc[mt][nt][1]),
                          "+r"(acc[mt][nt][2]), "+r"(acc[mt][nt][3])
                        : "r"(af[mt][0]), "r"(af[mt][1]),
                          "r"(af[mt][2]), "r"(af[mt][3]),
                          "r"(bf[nt >> 1][(nt & 1) * 2]),
                          "r"(bf[nt >> 1][(nt & 1) * 2 + 1]));
                }
        }
    }
    __syncthreads();

    const int g = lane >> 2, tig = lane & 3;
    // ---- row maxes: row = wm + mt*16 + g + p*8 ----
    #pragma unroll
    for (int mt = 0; mt < 4; mt++)
        #pragma unroll
        for (int p = 0; p < 2; p++) {
            int m = -2000000000;
            #pragma unroll
            for (int nt = 0; nt < 4; nt++) {
                m = max(m, acc[mt][nt][p * 2 + 0]);
                m = max(m, acc[mt][nt][p * 2 + 1]);
            }
            m = max(m, __shfl_xor_sync(0xffffffffu, m, 1));
            m = max(m, __shfl_xor_sync(0xffffffffu, m, 2));
            if (tig == 0) atomicMax(&srow[wm + mt * 16 + g + p * 8], m);
        }
    // ---- col maxes: col = wn + nt*8 + tig*2 + q ----
    #pragma unroll
    for (int nt = 0; nt < 4; nt++)
        #pragma unroll
        for (int q = 0; q < 2; q++) {
            int m = -2000000000;
            #pragma unroll
            for (int mt = 0; mt < 4; mt++) {
                m = max(m, acc[mt][nt][q]);
                m = max(m, acc[mt][nt][2 + q]);
            }
            m = max(m, __shfl_xor_sync(0xffffffffu, m, 4));
            m = max(m, __shfl_xor_sync(0xffffffffu, m, 8));
            m = max(m, __shfl_xor_sync(0xffffffffu, m, 16));
            if (g == 0) atomicMax(&scol[wn + nt * 8 + tig * 2 + q], m);
        }

    __syncthreads();
    if (tid < BM) atomicMax(&g_rowmax[m0 + tid], srow[tid]);
    if (tid < BN) atomicMax(&g_colmax[n0 + tid], scol[tid]);

    // ---- fused finalize: last CTA computes the entropy sums ----
    __threadfence();
    if (tid == 0) is_last = (atomicAdd(&g_done, 1) == NCTA - 1) ? 1 : 0;
    __syncthreads();
    if (!is_last) return;

    const float LOG_NORM = -0.69579514f;  // -log(0.8) - 0.5*log(2*pi)
    const float INV2S2   = 0.78125f;      // 1 / (2 * 0.8^2)
    float s1 = 0.f, s2 = 0.f;
    for (int i = tid; i < NROWS; i += 512) {
        float c = (float)__ldcg(&g_rowmax[i]) * INV_Q2;
        float lp = -(c * c) * INV2S2 + LOG_NORM;
        s1 -= __expf(lp) * lp;
        c = (float)__ldcg(&g_colmax[i]) * INV_Q2;
        lp = -(c * c) * INV2S2 + LOG_NORM;
        s2 -= __expf(lp) * lp;
    }
    #pragma unroll
    for (int o = 16; o > 0; o >>= 1) {
        s1 += __shfl_xor_sync(0xffffffffu, s1, o);
        s2 += __shfl_xor_sync(0xffffffffu, s2, o);
    }
    __shared__ float w1[16], w2[16];
    if ((tid & 31) == 0) { w1[tid >> 5] = s1; w2[tid >> 5] = s2; }
    __syncthreads();
    if (tid < 16) {
        float t1 = w1[tid], t2 = w2[tid];
        #pragma unroll
        for (int o = 8; o > 0; o >>= 1) {
            t1 += __shfl_xor_sync(0xffffu, t1, o);
            t2 += __shfl_xor_sync(0xffffu, t2, o);
        }
        if (tid == 0) { out[0] = t1; out[1] = t2; }
    }
}

// ---------------------------------------------------------------------------
extern "C" void kernel_launch(void* const* d_in, const int* in_sizes, int n_in,
                              void* d_out, int out_size) {
    (void)in_sizes; (void)n_in; (void)out_size;
    const float* ex = (const float*)d_in[0];
    const float* ey = (const float*)d_in[1];
    float* out = (float*)d_out;

    cudaFuncSetAttribute(gemm_max_kernel,
                         cudaFuncAttributeMaxDynamicSharedMemorySize, SMEM_TOTAL);

    norm_kernel<<<2 * NROWS / 8, 256>>>(ex, ey);
    init_kernel<<<(NROWS + 255) / 256, 256>>>();
    dim3 grid(NROWS / BN, NROWS / BM);   // 32 x 64
    gemm_max_kernel<<<grid, 512, SMEM_TOTAL>>>(out);
}

// round 7
// speedup vs baseline: 3.0084x; 3.0084x over previous
#include <cuda_runtime.h>
#include <cuda_bf16.h>
#include <cstdint>
#include <math.h>

// C = normalize_rows(ex) @ normalize_rows(ey)^T  [8192 x 8192]
// rowmax/colmax -> entropy terms. bf16 mma.sync GEMM, 128x128 CTA tile,
// 2 CTAs/SM (cross-CTA latency hiding), 2-stage cp.async, fused epilogue +
// fused finalize. C never materialized.

#define NROWS 8192
#define KDIM  768
#define BM 128
#define BN 128
#define BK 64                  // 64 bf16 = 128B rows
#define NK (KDIM / BK)         // 12
#define A_BYTES (BM * BK * 2)  // 16384
#define B_BYTES (BN * BK * 2)  // 16384
#define STAGE_BYTES (A_BYTES + B_BYTES)   // 32768
#define SMEM_TOTAL (2 * STAGE_BYTES)      // 65536
#define NCTA ((NROWS / BM) * (NROWS / BN))  // 4096

__device__ __align__(128) __nv_bfloat16 g_Xn[NROWS * KDIM];
__device__ __align__(128) __nv_bfloat16 g_Yn[NROWS * KDIM];
__device__ float g_rowmax[NROWS];
__device__ float g_colmax[NROWS];
__device__ int g_done;

__device__ __forceinline__ void atomicMaxF(float* addr, float v) {
    if (v >= 0.f) atomicMax((int*)addr, __float_as_int(v));
    else          atomicMin((unsigned int*)addr, __float_as_uint(v));
}
__device__ __forceinline__ uint32_t s2u(const void* p) {
    return (uint32_t)__cvta_generic_to_shared(p);
}

// ---------------------------------------------------------------------------
// Kernel 1: row-normalize fp32 -> bf16. Warp per row, 8 rows per block.
// ---------------------------------------------------------------------------
__global__ __launch_bounds__(256) void norm_kernel(const float* __restrict__ ex,
                                                   const float* __restrict__ ey) {
    int warp = threadIdx.x >> 5, lane = threadIdx.x & 31;
    int row = blockIdx.x * 8 + warp;
    const float* src;
    __nv_bfloat16* dst;
    if (row < NROWS) { src = ex + (size_t)row * KDIM; dst = g_Xn + (size_t)row * KDIM; }
    else { row -= NROWS; src = ey + (size_t)row * KDIM; dst = g_Yn + (size_t)row * KDIM; }

    float4 v[6];
    float ss = 0.f;
    #pragma unroll
    for (int w = 0; w < 6; w++) {
        v[w] = ((const float4*)src)[lane + w * 32];
        ss += v[w].x * v[w].x + v[w].y * v[w].y + v[w].z * v[w].z + v[w].w * v[w].w;
    }
    #pragma unroll
    for (int o = 16; o > 0; o >>= 1) ss += __shfl_xor_sync(0xffffffffu, ss, o);
    float inv = 1.0f / fmaxf(sqrtf(ss), 1e-8f);
    #pragma unroll
    for (int w = 0; w < 6; w++) {
        __nv_bfloat162 lo = __floats2bfloat162_rn(v[w].x * inv, v[w].y * inv);
        __nv_bfloat162 hi = __floats2bfloat162_rn(v[w].z * inv, v[w].w * inv);
        uint2 packed;
        packed.x = *(uint32_t*)&lo;
        packed.y = *(uint32_t*)&hi;
        ((uint2*)dst)[lane + w * 32] = packed;
    }
}

__global__ void init_kernel() {
    int t = blockIdx.x * blockDim.x + threadIdx.x;
    if (t < NROWS) { g_rowmax[t] = -2.f; g_colmax[t] = -2.f; }
    if (t == 0) g_done = 0;
}

// ---------------------------------------------------------------------------
// Kernel 3: bf16 GEMM, 128x128 CTA tile, 8 warps (64x32 warp tiles),
// BK=64, 2-stage cp.async, 2 CTAs/SM, fused row/col max + finalize.
// Swizzle: sw(row, kh) = row*128 + ((kh ^ (row & 7)) << 4), kh = 16B chunk.
// ---------------------------------------------------------------------------
__global__ __launch_bounds__(256, 2) void gemm_max_kernel(float* __restrict__ out) {
    extern __shared__ __align__(1024) char smem[];
    __shared__ float srow[BM];
    __shared__ float scol[BN];
    __shared__ int is_last;

    const int tid = threadIdx.x;
    const int warp = tid >> 5, lane = tid & 31;
    const int m0 = blockIdx.y * BM;
    const int n0 = blockIdx.x * BN;
    const int wm = (warp >> 2) * 64;   // 0 or 64
    const int wn = (warp & 3) * 32;    // 0..96

    if (tid < BM) srow[tid] = -2.f;
    if (tid < BN) scol[tid] = -2.f;

    float acc[4][4][4];
    #pragma unroll
    for (int a = 0; a < 4; a++)
        #pragma unroll
        for (int b = 0; b < 4; b++)
            #pragma unroll
            for (int c = 0; c < 4; c++) acc[a][b][c] = 0.f;

    auto prefetch = [&](int stage, int k0, bool valid) {
        if (valid) {
            char* sa = smem + stage * STAGE_BYTES;
            char* sb = sa + A_BYTES;
            #pragma unroll
            for (int j = 0; j < 8; j++) {
                int i = tid + j * 256;  // 0..2047 chunks of 16B
                const __nv_bfloat16* src;
                uint32_t dst;
                if (i < 1024) {         // A: 128 rows x 8 chunks
                    int row = i >> 3, kh = i & 7;
                    src = g_Xn + (size_t)(m0 + row) * KDIM + k0 + kh * 8;
                    dst = s2u(sa + row * 128 + ((kh ^ (row & 7)) << 4));
                } else {                // B: 128 rows x 8 chunks
                    int idx = i - 1024;
                    int row = idx >> 3, kh = idx & 7;
                    src = g_Yn + (size_t)(n0 + row) * KDIM + k0 + kh * 8;
                    dst = s2u(sb + row * 128 + ((kh ^ (row & 7)) << 4));
                }
                asm volatile("cp.async.cg.shared.global [%0], [%1], 16;"
                             :: "r"(dst), "l"(src));
            }
        }
        asm volatile("cp.async.commit_group;");
    };

    prefetch(0, 0, true);

    for (int it = 0; it < NK; it++) {
        asm volatile("cp.async.wait_group 0;");
        __syncthreads();
        // Prefetch the next stage before computing this one (depth-1 overlap;
        // the stage being overwritten was fully consumed last iteration, and
        // the syncthreads above ordered those reads before these writes).
        prefetch((it + 1) & 1, (it + 1) * BK, it + 1 < NK);

        const uint32_t sa = s2u(smem) + (uint32_t)(it & 1) * STAGE_BYTES;
        const uint32_t sb = sa + A_BYTES;

        #pragma unroll
        for (int kk = 0; kk < 4; kk++) {
            uint32_t af[4][4], bf[2][4];
            #pragma unroll
            for (int mt = 0; mt < 4; mt++) {
                int row = wm + mt * 16 + (lane & 15);
                int kh = kk * 2 + (lane >> 4);
                uint32_t addr = sa + row * 128 + ((kh ^ (row & 7)) << 4);
                asm volatile(
                    "ldmatrix.sync.aligned.m8n8.x4.shared.b16 {%0,%1,%2,%3}, [%4];"
                    : "=r"(af[mt][0]), "=r"(af[mt][1]),
                      "=r"(af[mt][2]), "=r"(af[mt][3]) : "r"(addr));
            }
            #pragma unroll
            for (int p = 0; p < 2; p++) {
                int n = wn + p * 16 + ((lane >> 4) << 3) + (lane & 7);
                int kh = kk * 2 + ((lane >> 3) & 1);
                uint32_t addr = sb + n * 128 + ((kh ^ (n & 7)) << 4);
                asm volatile(
                    "ldmatrix.sync.aligned.m8n8.x4.shared.b16 {%0,%1,%2,%3}, [%4];"
                    : "=r"(bf[p][0]), "=r"(bf[p][1]),
                      "=r"(bf[p][2]), "=r"(bf[p][3]) : "r"(addr));
            }
            #pragma unroll
            for (int mt = 0; mt < 4; mt++)
                #pragma unroll
                for (int nt = 0; nt < 4; nt++) {
                    asm volatile(
                        "mma.sync.aligned.m16n8k16.row.col.f32.bf16.bf16.f32 "
                        "{%0,%1,%2,%3}, {%4,%5,%6,%7}, {%8,%9}, {%0,%1,%2,%3};\n"
                        : "+f"(acc[mt][nt][0]), "+f"(acc[mt][nt][1]),
                          "+f"(acc[mt][nt][2]), "+f"(acc[mt][nt][3])
                        : "r"(af[mt][0]), "r"(af[mt][1]),
                          "r"(af[mt][2]), "r"(af[mt][3]),
                          "r"(bf[nt >> 1][(nt & 1) * 2]),
                          "r"(bf[nt >> 1][(nt & 1) * 2 + 1]));
                }
        }
        __syncthreads();
    }

    const int g = lane >> 2, tig = lane & 3;
    // ---- row maxes: row = wm + mt*16 + g + p*8 ----
    #pragma unroll
    for (int mt = 0; mt < 4; mt++)
        #pragma unroll
        for (int p = 0; p < 2; p++) {
            float m = -2.f;
            #pragma unroll
            for (int nt = 0; nt < 4; nt++) {
                m = fmaxf(m, acc[mt][nt][p * 2 + 0]);
                m = fmaxf(m, acc[mt][nt][p * 2 + 1]);
            }
            m = fmaxf(m, __shfl_xor_sync(0xffffffffu, m, 1));
            m = fmaxf(m, __shfl_xor_sync(0xffffffffu, m, 2));
            if (tig == 0) atomicMaxF(&srow[wm + mt * 16 + g + p * 8], m);
        }
    // ---- col maxes: col = wn + nt*8 + tig*2 + q ----
    #pragma unroll
    for (int nt = 0; nt < 4; nt++)
        #pragma unroll
        for (int q = 0; q < 2; q++) {
            float m = -2.f;
            #pragma unroll
            for (int mt = 0; mt < 4; mt++) {
                m = fmaxf(m, acc[mt][nt][q]);
                m = fmaxf(m, acc[mt][nt][2 + q]);
            }
            m = fmaxf(m, __shfl_xor_sync(0xffffffffu, m, 4));
            m = fmaxf(m, __shfl_xor_sync(0xffffffffu, m, 8));
            m = fmaxf(m, __shfl_xor_sync(0xffffffffu, m, 16));
            if (g == 0) atomicMaxF(&scol[wn + nt * 8 + tig * 2 + q], m);
        }

    __syncthreads();
    if (tid < BM) atomicMaxF(&g_rowmax[m0 + tid], srow[tid]);
    if (tid < BN) atomicMaxF(&g_colmax[n0 + tid], scol[tid]);

    // ---- fused finalize: last CTA computes the entropy sums ----
    __threadfence();
    if (tid == 0) is_last = (atomicAdd(&g_done, 1) == NCTA - 1) ? 1 : 0;
    __syncthreads();
    if (!is_last) return;

    const float LOG_NORM = -0.69579514f;  // -log(0.8) - 0.5*log(2*pi)
    const float INV2S2   = 0.78125f;      // 1 / (2 * 0.8^2)
    float s1 = 0.f, s2 = 0.f;
    for (int i = tid; i < NROWS; i += 256) {
        float c = __int_as_float(__ldcg((int*)&g_rowmax[i]));
        float lp = -(c * c) * INV2S2 + LOG_NORM;
        s1 -= __expf(lp) * lp;
        c = __int_as_float(__ldcg((int*)&g_colmax[i]));
        lp = -(c * c) * INV2S2 + LOG_NORM;
        s2 -= __expf(lp) * lp;
    }
    #pragma unroll
    for (int o = 16; o > 0; o >>= 1) {
        s1 += __shfl_xor_sync(0xffffffffu, s1, o);
        s2 += __shfl_xor_sync(0xffffffffu, s2, o);
    }
    __shared__ float w1[8], w2[8];
    if ((tid & 31) == 0) { w1[tid >> 5] = s1; w2[tid >> 5] = s2; }
    __syncthreads();
    if (tid == 0) {
        float t1 = 0.f, t2 = 0.f;
        #pragma unroll
        for (int i = 0; i < 8; i++) { t1 += w1[i]; t2 += w2[i]; }
        out[0] = t1;
        out[1] = t2;
    }
}

// ---------------------------------------------------------------------------
extern "C" void kernel_launch(void* const* d_in, const int* in_sizes, int n_in,
                              void* d_out, int out_size) {
    (void)in_sizes; (void)n_in; (void)out_size;
    const float* ex = (const float*)d_in[0];
    const float* ey = (const float*)d_in[1];
    float* out = (float*)d_out;

    cudaFuncSetAttribute(gemm_max_kernel,
                         cudaFuncAttributeMaxDynamicSharedMemorySize, SMEM_TOTAL);

    norm_kernel<<<2 * NROWS / 8, 256>>>(ex, ey);
    init_kernel<<<(NROWS + 255) / 256, 256>>>();
    dim3 grid(NROWS / BN, NROWS / BM);   // 64 x 64
    gemm_max_kernel<<<grid, 256, SMEM_TOTAL>>>(out);
}